// round 5
// baseline (speedup 1.0000x reference)
#include <cuda_runtime.h>
#include <cstdint>

#define B 64
#define P 8732
#define C 81
#define O 32
#define RPB 128          // rows per block in loss kernel (B*P = 558848 = 128*4366)
#define NSLICE 8
#define CHUNK 1092       // ceil(P/NSLICE)

#define NEG_INF (__int_as_float(0xff800000))

// ---------------- scratch (device globals; no allocation anywhere) ----------
__device__ unsigned long long g_obj_slice[B * NSLICE * O]; // per (b,slice,o) best prior
__device__ int   g_match[B * P];                 // packed (obj<<8)|tc per prior
__device__ float g_mined[B * P];                 // bg_loss (neg) / -inf (pos)
__device__ int   g_num_pos[B];
__device__ float g_neg_sum[B];
__device__ float g_pos_ce;
__device__ float g_sl1;
__device__ int   g_done;

// ---------------- helpers ----------------------------------------------------
__device__ __forceinline__ unsigned okey(float f) {
    unsigned u = __float_as_uint(f);
    return (u & 0x80000000u) ? ~u : (u | 0x80000000u);   // monotone float->uint
}
__device__ __forceinline__ float fromkey(unsigned k) {
    unsigned u = (k & 0x80000000u) ? (k & 0x7FFFFFFFu) : ~k;
    return __uint_as_float(u);
}
__device__ __forceinline__ float smoothl1(float d) {
    float a = fabsf(d);
    return (a < 1.0f) ? 0.5f * a * a : a - 0.5f;
}
__device__ __forceinline__ float iou_f(float4 bx, float barea,
                                       float px0, float py0, float px1, float py1,
                                       float parea) {
    float lx = fmaxf(bx.x, px0), ly = fmaxf(bx.y, py0);
    float hx = fminf(bx.z, px1), hy = fminf(bx.w, py1);
    float w = fmaxf(hx - lx, 0.0f), h = fmaxf(hy - ly, 0.0f);
    float inter = w * h;
    return inter / (barea + parea - inter);
}

// ---------------- K1: fused matching (per-prior + per-object) + init ----------
__global__ void __launch_bounds__(256) match_kernel(const float* __restrict__ boxes,
                                                    const int*   __restrict__ labels,
                                                    const float* __restrict__ priors) {
    int slice = blockIdx.x;          // 0..7
    int b = blockIdx.y;
    int tid = threadIdx.x;
    __shared__ float4 sbox[O];
    __shared__ float  sarea[O];
    __shared__ int    slab[O];
    __shared__ unsigned long long sobj[O];
    if (tid < O) {
        float4 bx = ((const float4*)boxes)[b * O + tid];
        sbox[tid] = bx;
        sarea[tid] = (bx.z - bx.x) * (bx.w - bx.y);
        slab[tid] = labels[b * O + tid];
        sobj[tid] = 0ULL;
    }
    if (slice == 0 && b == 0) {      // init accumulators (consumed by later launches)
        if (tid < B) { g_num_pos[tid] = 0; g_neg_sum[tid] = 0.0f; }
        if (tid == 0) { g_pos_ce = 0.0f; g_sl1 = 0.0f; g_done = 0; }
    }
    __syncthreads();

    int pstart = slice * CHUNK;
    int pend = min(P, pstart + CHUNK);

    // phase A: per-prior argmax over 32 objects
    for (int p = pstart + tid; p < pend; p += 256) {
        float4 pr = ((const float4*)priors)[p];
        float px0 = pr.x - 0.5f * pr.z, py0 = pr.y - 0.5f * pr.w;
        float px1 = pr.x + 0.5f * pr.z, py1 = pr.y + 0.5f * pr.w;
        float parea = pr.z * pr.w;
        float best_ov = -1.0f; int best_o = 0;
#pragma unroll
        for (int o = 0; o < O; o++) {
            float ov = iou_f(sbox[o], sarea[o], px0, py0, px1, py1, parea);
            if (ov > best_ov) { best_ov = ov; best_o = o; }   // first max = lowest o
        }
        int tc = (best_ov < 0.5f) ? 0 : slab[best_o];
        g_match[b * P + p] = (best_o << 8) | tc;
    }

    // phase B: per-object best prior, 8 objects per pass (priors now L1-resident)
    for (int og = 0; og < O / 8; og++) {
        unsigned long long acc[8];
#pragma unroll
        for (int j = 0; j < 8; j++) acc[j] = 0ULL;
        for (int p = pstart + tid; p < pend; p += 256) {
            float4 pr = ((const float4*)priors)[p];
            float px0 = pr.x - 0.5f * pr.z, py0 = pr.y - 0.5f * pr.w;
            float px1 = pr.x + 0.5f * pr.z, py1 = pr.y + 0.5f * pr.w;
            float parea = pr.z * pr.w;
            unsigned low = 0xFFFFFFFFu - (unsigned)p;          // lower p wins ties
#pragma unroll
            for (int j = 0; j < 8; j++) {
                int o = og * 8 + j;
                float ov = iou_f(sbox[o], sarea[o], px0, py0, px1, py1, parea);
                unsigned long long packed =
                    ((unsigned long long)__float_as_uint(ov) << 32) | low;
                if (packed > acc[j]) acc[j] = packed;
            }
        }
#pragma unroll
        for (int j = 0; j < 8; j++) atomicMax(&sobj[og * 8 + j], acc[j]);
    }
    __syncthreads();
    if (tid < O) g_obj_slice[(b * NSLICE + slice) * O + tid] = sobj[tid];
}

// ---------------- K2: smem-tiled losses + scatter-fold + mining scores -------
__global__ void __launch_bounds__(RPB) loss_kernel(const float* __restrict__ locs,
                            const float* __restrict__ scores,
                            const int*   __restrict__ labels,
                            const float* __restrict__ boxes,
                            const float* __restrict__ priors) {
    __shared__ float sm[RPB * C];                  // 41472 bytes
    __shared__ unsigned spriorF[2][O];
    __shared__ int slabF[2][O];
    size_t row0 = (size_t)blockIdx.x * RPB;
    int b0 = (int)(row0 / P);

    if (threadIdx.x < 64) {                        // reduce 8 slices -> forced priors
        int bi = threadIdx.x >> 5, o = threadIdx.x & 31;
        int bb = min(b0 + bi, B - 1);
        unsigned long long m = 0ULL;
#pragma unroll
        for (int s = 0; s < NSLICE; s++)
            m = max(m, g_obj_slice[(bb * NSLICE + s) * O + o]);
        spriorF[bi][o] = 0xFFFFFFFFu - (unsigned)(m & 0xFFFFFFFFu);
        slabF[bi][o] = labels[bb * O + o];
    }

    // stage 128 rows flat (16B-aligned: 128*81*4 = 41472)
    const float4* src = (const float4*)(scores + row0 * C);
    float4* dst = (float4*)sm;
    const int N4 = RPB * C / 4;                    // 2592
#pragma unroll 4
    for (int i = threadIdx.x; i < N4; i += RPB) dst[i] = src[i];
    __syncthreads();

    int r = (int)row0 + threadIdx.x;
    int b = r / P;
    int p = r - b * P;
    const float* my = sm + threadIdx.x * C;        // stride 81 words: conflict-free

    float s0 = 0.f, s1 = 0.f, s2 = 0.f, s3 = 0.f;
#pragma unroll
    for (int j = 0; j < 80; j += 4) {
        s0 += __expf(my[j]);
        s1 += __expf(my[j + 1]);
        s2 += __expf(my[j + 2]);
        s3 += __expf(my[j + 3]);
    }
    float sum = ((s0 + s1) + (s2 + s3)) + __expf(my[80]);
    float lse = __logf(sum);

    int mm = g_match[r];
    int tc = mm & 0xFF;
    int obj = mm >> 8;
    int bi = b - b0;
#pragma unroll
    for (int o = 0; o < O; o++) {                  // ascending: last (highest o) wins
        if (spriorF[bi][o] == (unsigned)p) { tc = slabF[bi][o]; obj = o; }
    }

    float mined;
    if (tc > 0) {
        atomicAdd(&g_pos_ce, lse - my[tc]);
        atomicAdd(&g_num_pos[b], 1);
        float4 bx = ((const float4*)boxes)[b * O + obj];
        float4 pr = ((const float4*)priors)[p];
        float cx = 0.5f * (bx.x + bx.z), cy = 0.5f * (bx.y + bx.w);
        float w = bx.z - bx.x, h = bx.w - bx.y;
        float t0 = (cx - pr.x) * 10.0f / pr.z;
        float t1 = (cy - pr.y) * 10.0f / pr.w;
        float t2 = __logf(w / pr.z) * 5.0f;
        float t3 = __logf(h / pr.w) * 5.0f;
        float4 pl = ((const float4*)locs)[r];
        float sl = smoothl1(pl.x - t0) + smoothl1(pl.y - t1) +
                   smoothl1(pl.z - t2) + smoothl1(pl.w - t3);
        atomicAdd(&g_sl1, sl);
        mined = NEG_INF;
    } else {
        mined = lse - my[0];
    }
    g_mined[r] = mined;
}

// ---------------- K3: per-batch radix-select top-K + fused finalize ----------
__global__ void __launch_bounds__(256) select_kernel(float* __restrict__ out) {
    int b = blockIdx.x;
    int tid = threadIdx.x;
    const float* mined = g_mined + b * P;

    __shared__ int hist[256];
    __shared__ int ssum[256];
    __shared__ unsigned sprefix;
    __shared__ int sK;
    __shared__ float swsum[8];
    __shared__ int slastf;

    int np = g_num_pos[b];
    int K = min(3 * np, P - np);
    float result = 0.0f;

    if (K > 0) {
        if (tid == 0) { sprefix = 0u; sK = K; }
        __syncthreads();
        for (int shift = 24; shift >= 0; shift -= 8) {
            hist[tid] = 0;
            __syncthreads();
            unsigned prefix = sprefix;
            int Kr = sK;
            for (int p = tid; p < P; p += 256) {
                unsigned k = okey(mined[p]);
                if (shift == 24 || (k >> (shift + 8)) == prefix)
                    atomicAdd(&hist[(k >> shift) & 255u], 1);
            }
            __syncthreads();
            // parallel suffix sum of hist
            ssum[tid] = hist[tid];
            __syncthreads();
#pragma unroll
            for (int s = 1; s < 256; s <<= 1) {
                int v = (tid + s < 256) ? ssum[tid + s] : 0;
                __syncthreads();
                ssum[tid] += v;
                __syncthreads();
            }
            int mine = ssum[tid];
            int nxt = (tid < 255) ? ssum[tid + 1] : 0;
            if (mine >= Kr && nxt < Kr) {           // unique tid
                sprefix = (prefix << 8) | (unsigned)tid;
                sK = Kr - nxt;
            }
            __syncthreads();
        }
        unsigned T = sprefix;
        int rr = sK;
        float Tval = fromkey(T);

        float sum = 0.0f;
        for (int p = tid; p < P; p += 256) {
            float v = mined[p];
            if (okey(v) > T) sum += v;
        }
#pragma unroll
        for (int off = 16; off; off >>= 1) sum += __shfl_xor_sync(0xFFFFFFFFu, sum, off);
        if ((tid & 31) == 0) swsum[tid >> 5] = sum;
        __syncthreads();
        if (tid == 0) {
            float tot = 0.0f;
            for (int i = 0; i < 8; i++) tot += swsum[i];
            result = tot + (float)rr * Tval;
        }
    }

    if (tid == 0) {
        g_neg_sum[b] = result;
        __threadfence();
        int d = atomicAdd(&g_done, 1);
        slastf = (d == B - 1);
    }
    __syncthreads();

    if (slastf) {                                  // last block finalizes
        __threadfence();
        float ns = 0.0f, npv = 0.0f;
        if (tid < B) {
            ns = *(volatile float*)&g_neg_sum[tid];
            npv = (float)*(volatile int*)&g_num_pos[tid];
        }
#pragma unroll
        for (int off = 16; off; off >>= 1) {
            ns += __shfl_xor_sync(0xFFFFFFFFu, ns, off);
            npv += __shfl_xor_sync(0xFFFFFFFFu, npv, off);
        }
        __shared__ float a2[2], c2[2];
        if (tid < B && (tid & 31) == 0) { a2[tid >> 5] = ns; c2[tid >> 5] = npv; }
        __syncthreads();
        if (tid == 0) {
            float totns = a2[0] + a2[1];
            float n = c2[0] + c2[1];
            out[0] = (g_pos_ce + totns) / n;
            out[1] = g_sl1 / n;
        }
    }
}

// ---------------- launch ------------------------------------------------------
extern "C" void kernel_launch(void* const* d_in, const int* in_sizes, int n_in,
                              void* d_out, int out_size) {
    const float* locs   = (const float*)d_in[0];   // [B,P,4]
    const float* scores = (const float*)d_in[1];   // [B,P,C]
    const float* boxes  = (const float*)d_in[2];   // [B,O,4] xy
    const int*   labels = (const int*)  d_in[3];   // [B,O]
    const float* priors = (const float*)d_in[4];   // [P,4] cxcywh
    float* out = (float*)d_out;

    match_kernel<<<dim3(NSLICE, B), 256>>>(boxes, labels, priors);
    loss_kernel<<<(B * P) / RPB, RPB>>>(locs, scores, labels, boxes, priors);
    select_kernel<<<B, 256>>>(out);
}

// round 6
// speedup vs baseline: 1.9108x; 1.9108x over previous
#include <cuda_runtime.h>
#include <cstdint>

#define B 64
#define P 8732
#define C 81
#define O 32
#define RPB 128          // rows per block in loss kernel (B*P = 558848 = 128*4366)
#define NSLICE 4
#define CHUNK 2183       // ceil(P/NSLICE)

#define NEG_INF (__int_as_float(0xff800000))

// ---------------- scratch (device globals; no allocation anywhere) ----------
__device__ unsigned long long g_obj_slice[B * NSLICE * O]; // per (b,slice,o) best prior
__device__ int   g_match[B * P];                 // packed (obj<<8)|tc per prior
__device__ float g_mined[B * P];                 // bg_loss (neg) / -inf (pos)
__device__ int   g_num_pos[B];
__device__ float g_neg_sum[B];
__device__ float g_pos_ce;
__device__ float g_sl1;
__device__ int   g_done;

// ---------------- helpers ----------------------------------------------------
__device__ __forceinline__ unsigned okey(float f) {
    unsigned u = __float_as_uint(f);
    return (u & 0x80000000u) ? ~u : (u | 0x80000000u);   // monotone float->uint
}
__device__ __forceinline__ float fromkey(unsigned k) {
    unsigned u = (k & 0x80000000u) ? (k & 0x7FFFFFFFu) : ~k;
    return __uint_as_float(u);
}
__device__ __forceinline__ float smoothl1(float d) {
    float a = fabsf(d);
    return (a < 1.0f) ? 0.5f * a * a : a - 0.5f;
}
__device__ __forceinline__ float iou_f(float4 bx, float barea,
                                       float px0, float py0, float px1, float py1,
                                       float parea) {
    float lx = fmaxf(bx.x, px0), ly = fmaxf(bx.y, py0);
    float hx = fminf(bx.z, px1), hy = fminf(bx.w, py1);
    float w = fmaxf(hx - lx, 0.0f), h = fmaxf(hy - ly, 0.0f);
    float inter = w * h;
    return inter / (barea + parea - inter);
}

// ---------------- K1a: per-prior argmax over objects (thread per prior) ------
// block (0,0) also initializes the global accumulators consumed downstream.
__global__ void __launch_bounds__(256) prior_match_kernel(
        const float* __restrict__ boxes,
        const int*   __restrict__ labels,
        const float* __restrict__ priors) {
    int b = blockIdx.y;
    int p = blockIdx.x * 256 + threadIdx.x;
    __shared__ float4 sbox[O];
    __shared__ float  sarea[O];
    __shared__ int    slab[O];
    if (threadIdx.x < O) {
        float4 bx = ((const float4*)boxes)[b * O + threadIdx.x];
        sbox[threadIdx.x] = bx;
        sarea[threadIdx.x] = (bx.z - bx.x) * (bx.w - bx.y);
        slab[threadIdx.x] = labels[b * O + threadIdx.x];
    }
    if (blockIdx.x == 0 && b == 0) {
        if (threadIdx.x < B) { g_num_pos[threadIdx.x] = 0; g_neg_sum[threadIdx.x] = 0.0f; }
        if (threadIdx.x == 0) { g_pos_ce = 0.0f; g_sl1 = 0.0f; g_done = 0; }
    }
    __syncthreads();
    if (p >= P) return;

    float4 pr = ((const float4*)priors)[p];       // cxcywh
    float px0 = pr.x - 0.5f * pr.z, py0 = pr.y - 0.5f * pr.w;
    float px1 = pr.x + 0.5f * pr.z, py1 = pr.y + 0.5f * pr.w;
    float parea = pr.z * pr.w;

    float best_ov = -1.0f; int best_o = 0;
#pragma unroll
    for (int o = 0; o < O; o++) {
        float ov = iou_f(sbox[o], sarea[o], px0, py0, px1, py1, parea);
        if (ov > best_ov) { best_ov = ov; best_o = o; }    // first max = lowest o
    }
    int tc = (best_ov < 0.5f) ? 0 : slab[best_o];
    g_match[b * P + p] = (best_o << 8) | tc;
}

// ---------------- K1b: per-object best prior (warp per object) ---------------
__global__ void __launch_bounds__(1024) object_match_kernel(
        const float* __restrict__ boxes,
        const float* __restrict__ priors) {
    int slice = blockIdx.x;                        // 0..NSLICE-1
    int b = blockIdx.y;
    int wid = threadIdx.x >> 5;                    // object id
    int lane = threadIdx.x & 31;
    __shared__ float4 sbox[O];
    __shared__ float  sarea[O];
    if (threadIdx.x < O) {
        float4 bx = ((const float4*)boxes)[b * O + threadIdx.x];
        sbox[threadIdx.x] = bx;
        sarea[threadIdx.x] = (bx.z - bx.x) * (bx.w - bx.y);
    }
    __syncthreads();
    float4 bx = sbox[wid];
    float barea = sarea[wid];

    int pstart = slice * CHUNK;
    int pend = min(P, pstart + CHUNK);

    unsigned long long best = 0ULL;
    for (int p = pstart + lane; p < pend; p += 32) {
        float4 pr = ((const float4*)priors)[p];
        float px0 = pr.x - 0.5f * pr.z, py0 = pr.y - 0.5f * pr.w;
        float px1 = pr.x + 0.5f * pr.z, py1 = pr.y + 0.5f * pr.w;
        float parea = pr.z * pr.w;
        float ov = iou_f(bx, barea, px0, py0, px1, py1, parea);   // ov >= 0
        unsigned long long packed =
            ((unsigned long long)__float_as_uint(ov) << 32) |
            (unsigned)(0xFFFFFFFFu - (unsigned)p);                // lower p wins ties
        if (packed > best) best = packed;
    }
#pragma unroll
    for (int off = 16; off; off >>= 1) {
        unsigned long long v = __shfl_xor_sync(0xFFFFFFFFu, best, off);
        if (v > best) best = v;
    }
    if (lane == 0) g_obj_slice[(b * NSLICE + slice) * O + wid] = best;
}

// ---------------- K2: smem-tiled losses + scatter-fold + mining scores -------
__global__ void __launch_bounds__(RPB) loss_kernel(const float* __restrict__ locs,
                            const float* __restrict__ scores,
                            const int*   __restrict__ labels,
                            const float* __restrict__ boxes,
                            const float* __restrict__ priors) {
    __shared__ float sm[RPB * C];                  // 41472 bytes
    __shared__ unsigned spriorF[2][O];
    __shared__ int slabF[2][O];
    size_t row0 = (size_t)blockIdx.x * RPB;
    int b0 = (int)(row0 / P);

    if (threadIdx.x < 64) {                        // reduce slices -> forced priors
        int bi = threadIdx.x >> 5, o = threadIdx.x & 31;
        int bb = min(b0 + bi, B - 1);
        unsigned long long m = 0ULL;
#pragma unroll
        for (int s = 0; s < NSLICE; s++)
            m = max(m, g_obj_slice[(bb * NSLICE + s) * O + o]);
        spriorF[bi][o] = 0xFFFFFFFFu - (unsigned)(m & 0xFFFFFFFFu);
        slabF[bi][o] = labels[bb * O + o];
    }

    // stage 128 rows flat (16B-aligned: 128*81*4 = 41472)
    const float4* src = (const float4*)(scores + row0 * C);
    float4* dst = (float4*)sm;
    const int N4 = RPB * C / 4;                    // 2592
#pragma unroll 4
    for (int i = threadIdx.x; i < N4; i += RPB) dst[i] = src[i];
    __syncthreads();

    int r = (int)row0 + threadIdx.x;
    int b = r / P;
    int p = r - b * P;
    const float* my = sm + threadIdx.x * C;        // stride 81 words: conflict-free

    float s0 = 0.f, s1 = 0.f, s2 = 0.f, s3 = 0.f;
#pragma unroll
    for (int j = 0; j < 80; j += 4) {
        s0 += __expf(my[j]);
        s1 += __expf(my[j + 1]);
        s2 += __expf(my[j + 2]);
        s3 += __expf(my[j + 3]);
    }
    float sum = ((s0 + s1) + (s2 + s3)) + __expf(my[80]);
    float lse = __logf(sum);

    int mm = g_match[r];
    int tc = mm & 0xFF;
    int obj = mm >> 8;
    int bi = b - b0;
#pragma unroll
    for (int o = 0; o < O; o++) {                  // ascending: last (highest o) wins
        if (spriorF[bi][o] == (unsigned)p) { tc = slabF[bi][o]; obj = o; }
    }

    float mined;
    if (tc > 0) {
        atomicAdd(&g_pos_ce, lse - my[tc]);
        atomicAdd(&g_num_pos[b], 1);
        float4 bx = ((const float4*)boxes)[b * O + obj];
        float4 pr = ((const float4*)priors)[p];
        float cx = 0.5f * (bx.x + bx.z), cy = 0.5f * (bx.y + bx.w);
        float w = bx.z - bx.x, h = bx.w - bx.y;
        float t0 = (cx - pr.x) * 10.0f / pr.z;
        float t1 = (cy - pr.y) * 10.0f / pr.w;
        float t2 = __logf(w / pr.z) * 5.0f;
        float t3 = __logf(h / pr.w) * 5.0f;
        float4 pl = ((const float4*)locs)[r];
        float sl = smoothl1(pl.x - t0) + smoothl1(pl.y - t1) +
                   smoothl1(pl.z - t2) + smoothl1(pl.w - t3);
        atomicAdd(&g_sl1, sl);
        mined = NEG_INF;
    } else {
        mined = lse - my[0];
    }
    g_mined[r] = mined;
}

// ---------------- K3: per-batch radix-select top-K + fused finalize ----------
__global__ void __launch_bounds__(256) select_kernel(float* __restrict__ out) {
    int b = blockIdx.x;
    int tid = threadIdx.x;
    const float* mined = g_mined + b * P;

    __shared__ int hist[256];
    __shared__ int ssum[256];
    __shared__ unsigned sprefix;
    __shared__ int sK;
    __shared__ float swsum[8];
    __shared__ int slastf;

    int np = g_num_pos[b];
    int K = min(3 * np, P - np);
    float result = 0.0f;

    if (K > 0) {
        if (tid == 0) { sprefix = 0u; sK = K; }
        __syncthreads();
        for (int shift = 24; shift >= 0; shift -= 8) {
            hist[tid] = 0;
            __syncthreads();
            unsigned prefix = sprefix;
            int Kr = sK;
            for (int p = tid; p < P; p += 256) {
                unsigned k = okey(mined[p]);
                if (shift == 24 || (k >> (shift + 8)) == prefix)
                    atomicAdd(&hist[(k >> shift) & 255u], 1);
            }
            __syncthreads();
            // parallel suffix sum of hist
            ssum[tid] = hist[tid];
            __syncthreads();
#pragma unroll
            for (int s = 1; s < 256; s <<= 1) {
                int v = (tid + s < 256) ? ssum[tid + s] : 0;
                __syncthreads();
                ssum[tid] += v;
                __syncthreads();
            }
            int mine = ssum[tid];
            int nxt = (tid < 255) ? ssum[tid + 1] : 0;
            if (mine >= Kr && nxt < Kr) {           // unique tid
                sprefix = (prefix << 8) | (unsigned)tid;
                sK = Kr - nxt;
            }
            __syncthreads();
        }
        unsigned T = sprefix;
        int rr = sK;
        float Tval = fromkey(T);

        float sum = 0.0f;
        for (int p = tid; p < P; p += 256) {
            float v = mined[p];
            if (okey(v) > T) sum += v;
        }
#pragma unroll
        for (int off = 16; off; off >>= 1) sum += __shfl_xor_sync(0xFFFFFFFFu, sum, off);
        if ((tid & 31) == 0) swsum[tid >> 5] = sum;
        __syncthreads();
        if (tid == 0) {
            float tot = 0.0f;
            for (int i = 0; i < 8; i++) tot += swsum[i];
            result = tot + (float)rr * Tval;
        }
    }

    if (tid == 0) {
        g_neg_sum[b] = result;
        __threadfence();
        int d = atomicAdd(&g_done, 1);
        slastf = (d == B - 1);
    }
    __syncthreads();

    if (slastf) {                                  // last block finalizes
        __threadfence();
        float ns = 0.0f, npv = 0.0f;
        if (tid < B) {
            ns = *(volatile float*)&g_neg_sum[tid];
            npv = (float)*(volatile int*)&g_num_pos[tid];
        }
#pragma unroll
        for (int off = 16; off; off >>= 1) {
            ns += __shfl_xor_sync(0xFFFFFFFFu, ns, off);
            npv += __shfl_xor_sync(0xFFFFFFFFu, npv, off);
        }
        __shared__ float a2[2], c2[2];
        if (tid < B && (tid & 31) == 0) { a2[tid >> 5] = ns; c2[tid >> 5] = npv; }
        __syncthreads();
        if (tid == 0) {
            float totns = a2[0] + a2[1];
            float n = c2[0] + c2[1];
            out[0] = (g_pos_ce + totns) / n;
            out[1] = g_sl1 / n;
        }
    }
}

// ---------------- launch ------------------------------------------------------
extern "C" void kernel_launch(void* const* d_in, const int* in_sizes, int n_in,
                              void* d_out, int out_size) {
    const float* locs   = (const float*)d_in[0];   // [B,P,4]
    const float* scores = (const float*)d_in[1];   // [B,P,C]
    const float* boxes  = (const float*)d_in[2];   // [B,O,4] xy
    const int*   labels = (const int*)  d_in[3];   // [B,O]
    const float* priors = (const float*)d_in[4];   // [P,4] cxcywh
    float* out = (float*)d_out;

    prior_match_kernel<<<dim3((P + 255) / 256, B), 256>>>(boxes, labels, priors);
    object_match_kernel<<<dim3(NSLICE, B), 1024>>>(boxes, priors);
    loss_kernel<<<(B * P) / RPB, RPB>>>(locs, scores, labels, boxes, priors);
    select_kernel<<<B, 256>>>(out);
}

// round 7
// speedup vs baseline: 2.0713x; 1.0840x over previous
#include <cuda_runtime.h>
#include <cstdint>

#define B 64
#define P 8732
#define C 81
#define O 32
#define RPB 128          // rows per loss block (B*P = 558848 = 128*4366)
#define NSLICE 4
#define CHUNK 2183       // P/NSLICE exactly

#define NEG_INF (__int_as_float(0xff800000))

// ---------------- scratch (device globals; no allocation anywhere) ----------
__device__ unsigned long long g_obj_slice[B * NSLICE * O]; // per (b,slice,o): (ov_bits<<32)|~p
__device__ int   g_match[B * P];                 // packed (obj<<8)|tc per prior
__device__ float g_mined[B * P];                 // bg_loss (neg) / -inf (pos)
__device__ int   g_num_pos[B];
__device__ float g_neg_sum[B];
__device__ float g_pos_ce;
__device__ float g_sl1;
__device__ int   g_done;

// ---------------- helpers ----------------------------------------------------
__device__ __forceinline__ unsigned okey(float f) {
    unsigned u = __float_as_uint(f);
    return (u & 0x80000000u) ? ~u : (u | 0x80000000u);
}
__device__ __forceinline__ float fromkey(unsigned k) {
    unsigned u = (k & 0x80000000u) ? (k & 0x7FFFFFFFu) : ~k;
    return __uint_as_float(u);
}
__device__ __forceinline__ float smoothl1(float d) {
    float a = fabsf(d);
    return (a < 1.0f) ? 0.5f * a * a : a - 0.5f;
}
// intersection and union (no division!)
__device__ __forceinline__ void inter_union(float4 bx, float barea,
                                            float px0, float py0, float px1, float py1,
                                            float parea, float& inter, float& uni) {
    float lx = fmaxf(bx.x, px0), ly = fmaxf(bx.y, py0);
    float hx = fminf(bx.z, px1), hy = fminf(bx.w, py1);
    float w = fmaxf(hx - lx, 0.0f), h = fmaxf(hy - ly, 0.0f);
    inter = w * h;
    uni = barea + parea - inter;
}

// ---------------- K1: fused matching (division-free) + init ------------------
__global__ void __launch_bounds__(1024) match_kernel(
        const float* __restrict__ boxes,
        const int*   __restrict__ labels,
        const float* __restrict__ priors) {
    int slice = blockIdx.x;          // 0..NSLICE-1
    int b = blockIdx.y;
    int tid = threadIdx.x;
    int wid = tid >> 5;              // 0..31 = object id for phase B
    int lane = tid & 31;
    __shared__ float4 sbox[O];
    __shared__ float  sarea[O];
    __shared__ int    slab[O];
    if (tid < O) {
        float4 bx = ((const float4*)boxes)[b * O + tid];
        sbox[tid] = bx;
        sarea[tid] = (bx.z - bx.x) * (bx.w - bx.y);
        slab[tid] = labels[b * O + tid];
    }
    if (slice == 0 && b == 0) {      // init accumulators for downstream launches
        if (tid < B) { g_num_pos[tid] = 0; g_neg_sum[tid] = 0.0f; }
        if (tid == 0) { g_pos_ce = 0.0f; g_sl1 = 0.0f; g_done = 0; }
    }
    __syncthreads();

    int pstart = slice * CHUNK;
    int pend = min(P, pstart + CHUNK);

    // ---- phase A: per-prior argmax over 32 objects (cross-mult compares) ----
    for (int p = pstart + tid; p < pend; p += 1024) {
        float4 pr = ((const float4*)priors)[p];
        float px0 = pr.x - 0.5f * pr.z, py0 = pr.y - 0.5f * pr.w;
        float px1 = pr.x + 0.5f * pr.z, py1 = pr.y + 0.5f * pr.w;
        float parea = pr.z * pr.w;
        float bi_, bu; int bo = 0;
        inter_union(sbox[0], sarea[0], px0, py0, px1, py1, parea, bi_, bu);
#pragma unroll
        for (int o = 1; o < O; o++) {
            float in2, un2;
            inter_union(sbox[o], sarea[o], px0, py0, px1, py1, parea, in2, un2);
            if (in2 * bu > bi_ * un2) { bi_ = in2; bu = un2; bo = o; }  // strict > keeps first max
        }
        int tc = (2.0f * bi_ < bu) ? 0 : slab[bo];   // ov < 0.5  <=>  2*inter < union
        g_match[b * P + p] = (bo << 8) | tc;
    }

    // ---- phase B: warp per object, best prior in this slice -----------------
    float4 bx = sbox[wid];
    float barea = sarea[wid];
    float bi_ = -1.0f, bu = 1.0f; unsigned bp = 0;
    for (int p = pstart + lane; p < pend; p += 32) {
        float4 pr = ((const float4*)priors)[p];
        float px0 = pr.x - 0.5f * pr.z, py0 = pr.y - 0.5f * pr.w;
        float px1 = pr.x + 0.5f * pr.z, py1 = pr.y + 0.5f * pr.w;
        float parea = pr.z * pr.w;
        float in2, un2;
        inter_union(bx, barea, px0, py0, px1, py1, parea, in2, un2);
        if (in2 * bu > bi_ * un2) { bi_ = in2; bu = un2; bp = (unsigned)p; }
    }
#pragma unroll
    for (int off = 16; off; off >>= 1) {
        float oi = __shfl_xor_sync(0xFFFFFFFFu, bi_, off);
        float ou = __shfl_xor_sync(0xFFFFFFFFu, bu, off);
        unsigned op = __shfl_xor_sync(0xFFFFFFFFu, bp, off);
        float l = oi * bu, r = bi_ * ou;
        if (l > r || (l == r && op < bp)) { bi_ = oi; bu = ou; bp = op; }
    }
    if (lane == 0) {
        float ov = bi_ / bu;                       // ONE division per (b,slice,o)
        g_obj_slice[(b * NSLICE + slice) * O + wid] =
            ((unsigned long long)__float_as_uint(ov) << 32) |
            (unsigned)(0xFFFFFFFFu - bp);          // lower p wins ties across slices
    }
}

// ---------------- K2: smem-tiled losses, 2 threads per row -------------------
__global__ void __launch_bounds__(256) loss_kernel(const float* __restrict__ locs,
                            const float* __restrict__ scores,
                            const int*   __restrict__ labels,
                            const float* __restrict__ boxes,
                            const float* __restrict__ priors) {
    __shared__ float sm[RPB * C];                  // 41472 bytes
    __shared__ unsigned spriorF[2][O];
    __shared__ int slabF[2][O];
    size_t row0 = (size_t)blockIdx.x * RPB;
    int b0 = (int)(row0 / P);

    if (threadIdx.x < 64) {                        // reduce slices -> forced priors
        int bi = threadIdx.x >> 5, o = threadIdx.x & 31;
        int bb = min(b0 + bi, B - 1);
        unsigned long long m = 0ULL;
#pragma unroll
        for (int s = 0; s < NSLICE; s++)
            m = max(m, g_obj_slice[(bb * NSLICE + s) * O + o]);
        spriorF[bi][o] = 0xFFFFFFFFu - (unsigned)(m & 0xFFFFFFFFu);
        slabF[bi][o] = labels[bb * O + o];
    }

    // stage 128 rows flat (row0*324 bytes, row0 mult of 128 -> 16B aligned)
    const float4* src = (const float4*)(scores + row0 * C);
    float4* dst = (float4*)sm;
    const int N4 = RPB * C / 4;                    // 2592
#pragma unroll 4
    for (int i = threadIdx.x; i < N4; i += 256) dst[i] = src[i];
    __syncthreads();

    int k = threadIdx.x >> 1;                      // local row
    int half = threadIdx.x & 1;
    const float* my = sm + k * C;

    float s0 = 0.f, s1 = 0.f, s2 = 0.f, s3 = 0.f;
#pragma unroll
    for (int j = half; j < 80; j += 8) {           // even/odd interleave
        s0 += __expf(my[j]);
        s1 += __expf(my[j + 2]);
        s2 += __expf(my[j + 4]);
        s3 += __expf(my[j + 6]);
    }
    float sum = (s0 + s1) + (s2 + s3);
    if (!half) sum += __expf(my[80]);
    sum += __shfl_xor_sync(0xFFFFFFFFu, sum, 1);   // pair lives in same warp
    float lse = __logf(sum);

    if (!half) {
        int r = (int)row0 + k;
        int b = r / P;
        int p = r - b * P;
        int bi = b - b0;

        int mm = g_match[r];
        int tc = mm & 0xFF;
        int obj = mm >> 8;
#pragma unroll
        for (int o = 0; o < O; o++) {              // ascending: last (highest o) wins
            if (spriorF[bi][o] == (unsigned)p) { tc = slabF[bi][o]; obj = o; }
        }

        float mined;
        if (tc > 0) {
            atomicAdd(&g_pos_ce, lse - my[tc]);
            atomicAdd(&g_num_pos[b], 1);
            float4 bx = ((const float4*)boxes)[b * O + obj];
            float4 pr = ((const float4*)priors)[p];
            float cx = 0.5f * (bx.x + bx.z), cy = 0.5f * (bx.y + bx.w);
            float w = bx.z - bx.x, h = bx.w - bx.y;
            float t0 = (cx - pr.x) * 10.0f / pr.z;
            float t1 = (cy - pr.y) * 10.0f / pr.w;
            float t2 = __logf(w / pr.z) * 5.0f;
            float t3 = __logf(h / pr.w) * 5.0f;
            float4 pl = ((const float4*)locs)[r];
            float sl = smoothl1(pl.x - t0) + smoothl1(pl.y - t1) +
                       smoothl1(pl.z - t2) + smoothl1(pl.w - t3);
            atomicAdd(&g_sl1, sl);
            mined = NEG_INF;
        } else {
            mined = lse - my[0];
        }
        g_mined[r] = mined;
    }
}

// ---------------- K3: per-batch radix-select top-K + fused finalize ----------
__global__ void __launch_bounds__(512) select_kernel(float* __restrict__ out) {
    int b = blockIdx.x;
    int tid = threadIdx.x;
    const float* mined = g_mined + b * P;

    __shared__ int hist[256];
    __shared__ int ssum[256];
    __shared__ int wtot[8];
    __shared__ unsigned sprefix;
    __shared__ int sK;
    __shared__ float swsum[16];
    __shared__ int slastf;

    int np = g_num_pos[b];
    int K = min(3 * np, P - np);
    float result = 0.0f;

    if (K > 0) {
        if (tid == 0) { sprefix = 0u; sK = K; }
        __syncthreads();
        for (int shift = 24; shift >= 0; shift -= 8) {
            if (tid < 256) hist[tid] = 0;
            __syncthreads();
            unsigned prefix = sprefix;
            int Kr = sK;
            for (int p = tid; p < P; p += 512) {
                unsigned k = okey(mined[p]);
                if (shift == 24 || (k >> (shift + 8)) == prefix)
                    atomicAdd(&hist[(k >> shift) & 255u], 1);
            }
            __syncthreads();
            int v = 0;
            int w = tid >> 5, l = tid & 31;
            if (tid < 256) {                       // warp-level suffix scan
                v = hist[tid];
#pragma unroll
                for (int off = 1; off < 32; off <<= 1) {
                    int u = __shfl_down_sync(0xFFFFFFFFu, v, off);
                    if (l + off < 32) v += u;
                }
                if (l == 0) wtot[w] = v;
            }
            __syncthreads();
            if (tid < 256) {
                int add = 0;
#pragma unroll
                for (int g = 1; g < 8; g++) if (w + g < 8) add += wtot[w + g];
                ssum[tid] = v + add;
            }
            __syncthreads();
            if (tid < 256) {
                int mine = ssum[tid];
                int nxt = (tid < 255) ? ssum[tid + 1] : 0;
                if (mine >= Kr && nxt < Kr) {      // unique tid
                    sprefix = (prefix << 8) | (unsigned)tid;
                    sK = Kr - nxt;
                }
            }
            __syncthreads();
        }
        unsigned T = sprefix;
        int rr = sK;
        float Tval = fromkey(T);

        float sum = 0.0f;
        for (int p = tid; p < P; p += 512) {
            float v2 = mined[p];
            if (okey(v2) > T) sum += v2;
        }
#pragma unroll
        for (int off = 16; off; off >>= 1) sum += __shfl_xor_sync(0xFFFFFFFFu, sum, off);
        if ((tid & 31) == 0) swsum[tid >> 5] = sum;
        __syncthreads();
        if (tid == 0) {
            float tot = 0.0f;
#pragma unroll
            for (int i = 0; i < 16; i++) tot += swsum[i];
            result = tot + (float)rr * Tval;
        }
    }

    if (tid == 0) {
        g_neg_sum[b] = result;
        __threadfence();
        int d = atomicAdd(&g_done, 1);
        slastf = (d == B - 1);
    }
    __syncthreads();

    if (slastf) {                                  // last block finalizes
        __threadfence();
        float ns = 0.0f, npv = 0.0f;
        if (tid < B) {
            ns = *(volatile float*)&g_neg_sum[tid];
            npv = (float)*(volatile int*)&g_num_pos[tid];
        }
#pragma unroll
        for (int off = 16; off; off >>= 1) {
            ns += __shfl_xor_sync(0xFFFFFFFFu, ns, off);
            npv += __shfl_xor_sync(0xFFFFFFFFu, npv, off);
        }
        __shared__ float a2[2], c2[2];
        if (tid < B && (tid & 31) == 0) { a2[tid >> 5] = ns; c2[tid >> 5] = npv; }
        __syncthreads();
        if (tid == 0) {
            float totns = a2[0] + a2[1];
            float n = c2[0] + c2[1];
            out[0] = (g_pos_ce + totns) / n;
            out[1] = g_sl1 / n;
        }
    }
}

// ---------------- launch ------------------------------------------------------
extern "C" void kernel_launch(void* const* d_in, const int* in_sizes, int n_in,
                              void* d_out, int out_size) {
    const float* locs   = (const float*)d_in[0];   // [B,P,4]
    const float* scores = (const float*)d_in[1];   // [B,P,C]
    const float* boxes  = (const float*)d_in[2];   // [B,O,4] xy
    const int*   labels = (const int*)  d_in[3];   // [B,O]
    const float* priors = (const float*)d_in[4];   // [P,4] cxcywh
    float* out = (float*)d_out;

    match_kernel<<<dim3(NSLICE, B), 1024>>>(boxes, labels, priors);
    loss_kernel<<<(B * P) / RPB, 256>>>(locs, scores, labels, boxes, priors);
    select_kernel<<<B, 512>>>(out);
}